// round 2
// baseline (speedup 1.0000x reference)
#include <cuda_runtime.h>

// Problem dims (fixed by setup_inputs)
#define BB 2048
#define NN 512
#define DD 256
#define NSTEPS 64
#define BN (BB * NN)

// Persistent scratch (allowed: __device__ globals, no runtime alloc)
__device__ float g_ic[BN];   // hoisted input current
__device__ float g_c0[BN];   // c double buffer 0
__device__ float g_c1[BN];   // c double buffer 1
__device__ float g_v[BN];    // membrane potential
__device__ float g_ss[BN];   // spike sum

// ---------------- packed f32x2 helpers (sm_103a FFMA2) ----------------
__device__ __forceinline__ unsigned long long pack2(float lo, float hi) {
    unsigned long long r;
    asm("mov.b64 %0, {%1, %2};" : "=l"(r) : "f"(lo), "f"(hi));
    return r;
}
__device__ __forceinline__ void unpack2(unsigned long long v, float& lo, float& hi) {
    asm("mov.b64 {%0, %1}, %2;" : "=f"(lo), "=f"(hi) : "l"(v));
}
__device__ __forceinline__ unsigned long long ffma2(unsigned long long a,
                                                    unsigned long long b,
                                                    unsigned long long c) {
    unsigned long long d;
    asm("fma.rn.f32x2 %0, %1, %2, %3;" : "=l"(d) : "l"(a), "l"(b), "l"(c));
    return d;
}

// ---------------- init: copy initial state, zero spike sum ----------------
__global__ void init_kernel(const float* __restrict__ v0, const float* __restrict__ c0) {
    int i = (blockIdx.x * blockDim.x + threadIdx.x) * 4;
    *(float4*)&g_c0[i] = *(const float4*)&c0[i];
    *(float4*)&g_v[i]  = *(const float4*)&v0[i];
    *(float4*)&g_ss[i] = make_float4(0.f, 0.f, 0.f, 0.f);
}

// ---------------- input current: IC = rates @ iw^T  (NT GEMM) ----------------
// rates: (BB, DD) row-major, iw: (NN, DD) row-major
__global__ __launch_bounds__(256) void ic_kernel(const float* __restrict__ rates,
                                                 const float* __restrict__ iw) {
    __shared__ float As[64][33];
    __shared__ float Bs[64][33];
    int bm = blockIdx.x * 64, bn = blockIdx.y * 64;
    int tid = threadIdx.x;
    int tx = tid & 15, ty = tid >> 4;
    float acc[4][4] = {};

    for (int k0 = 0; k0 < DD; k0 += 32) {
#pragma unroll
        for (int t = 0; t < 2; t++) {
            int idx = tid + t * 256;       // 0..511
            int r = idx >> 3, q = idx & 7; // 64 rows x 8 float4
            float4 a = *(const float4*)&rates[(bm + r) * DD + k0 + q * 4];
            As[r][q * 4 + 0] = a.x; As[r][q * 4 + 1] = a.y;
            As[r][q * 4 + 2] = a.z; As[r][q * 4 + 3] = a.w;
            float4 b = *(const float4*)&iw[(bn + r) * DD + k0 + q * 4];
            Bs[r][q * 4 + 0] = b.x; Bs[r][q * 4 + 1] = b.y;
            Bs[r][q * 4 + 2] = b.z; Bs[r][q * 4 + 3] = b.w;
        }
        __syncthreads();
#pragma unroll
        for (int k = 0; k < 32; k++) {
            float a[4], b[4];
#pragma unroll
            for (int i = 0; i < 4; i++) a[i] = As[ty * 4 + i][k];
#pragma unroll
            for (int j = 0; j < 4; j++) b[j] = Bs[tx * 4 + j][k];
#pragma unroll
            for (int i = 0; i < 4; i++)
#pragma unroll
                for (int j = 0; j < 4; j++)
                    acc[i][j] = fmaf(a[i], b[j], acc[i][j]);
        }
        __syncthreads();
    }
#pragma unroll
    for (int i = 0; i < 4; i++) {
        int row = bm + ty * 4 + i;
#pragma unroll
        for (int j = 0; j < 4; j++)
            g_ic[row * NN + bn + tx * 4 + j] = acc[i][j];
    }
}

// ---------------- fused step: rec = (c>0) @ W, then state update ----------------
// CTA tile 128(M) x 64(N), 256 threads, per-thread 8x4 via FFMA2 (4 m-pairs x 4 n)
__global__ __launch_bounds__(256) void step_kernel(const float* __restrict__ W, int s) {
    const float* __restrict__ c_in  = (s & 1) ? g_c1 : g_c0;
    float* __restrict__       c_out = (s & 1) ? g_c0 : g_c1;

    __shared__ __align__(16) float As[32][132];  // [k][m], padded (row = 528B, 16B-mult)
    __shared__ __align__(16) float Bs[32][64];   // [k][n]

    int bm = blockIdx.x * 128;
    int bn = blockIdx.y * 64;
    int tid = threadIdx.x;
    int tx = tid & 15, ty = tid >> 4;

    unsigned long long acc[4][4];
#pragma unroll
    for (int p = 0; p < 4; p++)
#pragma unroll
        for (int j = 0; j < 4; j++) acc[p][j] = 0ull;

    for (int k0 = 0; k0 < NN; k0 += 32) {
        // A tile: spikes from c_in, stored transposed As[k][m]
#pragma unroll
        for (int t = 0; t < 4; t++) {
            int idx = tid + t * 256;        // 0..1023
            int r = idx >> 3;               // row 0..127
            int q = idx & 7;                // k-quad 0..7
            float4 a = *(const float4*)&c_in[(bm + r) * NN + k0 + q * 4];
            As[q * 4 + 0][r] = a.x > 0.f ? 1.f : 0.f;
            As[q * 4 + 1][r] = a.y > 0.f ? 1.f : 0.f;
            As[q * 4 + 2][r] = a.z > 0.f ? 1.f : 0.f;
            As[q * 4 + 3][r] = a.w > 0.f ? 1.f : 0.f;
        }
        // B tile: W[k0+k][bn..bn+63]
#pragma unroll
        for (int t = 0; t < 2; t++) {
            int idx = tid + t * 256;        // 0..511
            int r = idx >> 4;               // k 0..31
            int q = idx & 15;               // n-quad
            *(float4*)&Bs[r][q * 4] = *(const float4*)&W[(k0 + r) * NN + bn + q * 4];
        }
        __syncthreads();
#pragma unroll
        for (int k = 0; k < 32; k++) {
            // a: 8 consecutive rows = 4 packed pairs (aligned 64-bit reads)
            ulonglong2 a01 = *(const ulonglong2*)&As[k][ty * 8];
            ulonglong2 a23 = *(const ulonglong2*)&As[k][ty * 8 + 4];
            unsigned long long ap[4] = { a01.x, a01.y, a23.x, a23.y };
            float4 bf = *(const float4*)&Bs[k][tx * 4];
            unsigned long long br[4] = { pack2(bf.x, bf.x), pack2(bf.y, bf.y),
                                         pack2(bf.z, bf.z), pack2(bf.w, bf.w) };
#pragma unroll
            for (int p = 0; p < 4; p++)
#pragma unroll
                for (int j = 0; j < 4; j++)
                    acc[p][j] = ffma2(ap[p], br[j], acc[p][j]);
        }
        __syncthreads();
    }

    // Fused epilogue: c' = as*c + (1-as)*(ic + rec); v' = am*v + (1-am)*c'; ss += (v'>0)
    const float AS = 0.81873075307798182f;
    const float OS = 0.18126924692201818f;
    const float AM = 0.95122942450071403f;
    const float OM = 0.04877057549928599f;

#pragma unroll
    for (int p = 0; p < 4; p++) {
        float lo[4], hi[4];
#pragma unroll
        for (int j = 0; j < 4; j++) unpack2(acc[p][j], lo[j], hi[j]);
#pragma unroll
        for (int h = 0; h < 2; h++) {
            int row = bm + ty * 8 + 2 * p + h;
            int base = row * NN + bn + tx * 4;
            float rec0 = h ? hi[0] : lo[0];
            float rec1 = h ? hi[1] : lo[1];
            float rec2 = h ? hi[2] : lo[2];
            float rec3 = h ? hi[3] : lo[3];
            float4 ci = *(const float4*)&c_in[base];
            float4 ic = *(const float4*)&g_ic[base];
            float4 vv = *(const float4*)&g_v[base];
            float4 ss = *(const float4*)&g_ss[base];
            float4 cn, vn;
            cn.x = AS * ci.x + OS * (ic.x + rec0);
            cn.y = AS * ci.y + OS * (ic.y + rec1);
            cn.z = AS * ci.z + OS * (ic.z + rec2);
            cn.w = AS * ci.w + OS * (ic.w + rec3);
            vn.x = AM * vv.x + OM * cn.x;
            vn.y = AM * vv.y + OM * cn.y;
            vn.z = AM * vv.z + OM * cn.z;
            vn.w = AM * vv.w + OM * cn.w;
            ss.x += (vn.x > 0.f) ? 1.f : 0.f;
            ss.y += (vn.y > 0.f) ? 1.f : 0.f;
            ss.z += (vn.z > 0.f) ? 1.f : 0.f;
            ss.w += (vn.w > 0.f) ? 1.f : 0.f;
            *(float4*)&c_out[base] = cn;
            *(float4*)&g_v[base]   = vn;
            *(float4*)&g_ss[base]  = ss;
        }
    }
}

// ---------------- finalize: out = [readout, v, c_final] ----------------
__global__ void finalize_kernel(float* __restrict__ out) {
    int i = (blockIdx.x * blockDim.x + threadIdx.x) * 4;
    float4 ss = *(const float4*)&g_ss[i];
    const float inv = 1.0f / (float)NSTEPS;
    float4 r = make_float4(ss.x * inv, ss.y * inv, ss.z * inv, ss.w * inv);
    *(float4*)&out[i]            = r;
    *(float4*)&out[BN + i]       = *(const float4*)&g_v[i];
    *(float4*)&out[2 * BN + i]   = *(const float4*)&g_c0[i];  // NSTEPS even -> final c in g_c0
}

extern "C" void kernel_launch(void* const* d_in, const int* in_sizes, int n_in,
                              void* d_out, int out_size) {
    const float* rates = (const float*)d_in[0];
    const float* iw    = (const float*)d_in[1];
    const float* W     = (const float*)d_in[2];
    const float* v0    = (const float*)d_in[3];
    const float* c0    = (const float*)d_in[4];
    float* out = (float*)d_out;

    init_kernel<<<BN / 1024, 256>>>(v0, c0);
    ic_kernel<<<dim3(BB / 64, NN / 64), 256>>>(rates, iw);
    for (int s = 0; s < NSTEPS; s++)
        step_kernel<<<dim3(BB / 128, NN / 64), 256>>>(W, s);
    finalize_kernel<<<BN / 1024, 256>>>(out);
}

// round 5
// speedup vs baseline: 2.3288x; 2.3288x over previous
#include <cuda_runtime.h>
#include <cuda_bf16.h>
#include <cstdint>

// Problem dims (fixed by setup_inputs)
#define BB 2048
#define NN 512
#define DD 256
#define NSTEPS 64
#define BN (BB * NN)

// Persistent scratch (__device__ globals; no runtime alloc)
__device__ float g_ic[BN];
__device__ float g_c0[BN];
__device__ float g_c1[BN];
__device__ float g_v[BN];
__device__ float g_ss[BN];
__device__ __nv_bfloat16 g_whi[NN * NN];   // W^T hi split, (n,k) row-major (k contiguous)
__device__ __nv_bfloat16 g_wlo[NN * NN];   // W^T lo split
__device__ __nv_bfloat16 g_spk0[BN];       // spike double buffer
__device__ __nv_bfloat16 g_spk1[BN];

// ---------------------------------------------------------------- helpers
__device__ __forceinline__ uint32_t smem_u32(const void* p) {
    uint32_t a;
    asm("{ .reg .u64 t; cvta.to.shared.u64 t, %1; cvt.u32.u64 %0, t; }" : "=r"(a) : "l"(p));
    return a;
}
__device__ __forceinline__ void cp16(uint32_t dst, const void* src) {
    asm volatile("cp.async.cg.shared.global [%0], [%1], 16;" :: "r"(dst), "l"(src));
}
#define CP_COMMIT() asm volatile("cp.async.commit_group;")
#define CP_WAIT(n)  asm volatile("cp.async.wait_group %0;" :: "n"(n))

#define LDSM_X4(r0, r1, r2, r3, addr) \
    asm volatile("ldmatrix.sync.aligned.m8n8.x4.shared.b16 {%0,%1,%2,%3}, [%4];" \
                 : "=r"(r0), "=r"(r1), "=r"(r2), "=r"(r3) : "r"(addr))

#define MMA16816(d, a0, a1, a2, a3, b0, b1) \
    asm volatile("mma.sync.aligned.m16n8k16.row.col.f32.bf16.bf16.f32 " \
                 "{%0,%1,%2,%3}, {%4,%5,%6,%7}, {%8,%9}, {%0,%1,%2,%3};" \
                 : "+f"((d)[0]), "+f"((d)[1]), "+f"((d)[2]), "+f"((d)[3]) \
                 : "r"(a0), "r"(a1), "r"(a2), "r"(a3), "r"(b0), "r"(b1))

#define SWZ(o) ((o) ^ (((o) >> 3) & 0x70))

// ---------------------------------------------------------------- init
__global__ void init_kernel(const float* __restrict__ v0, const float* __restrict__ c0) {
    int i = (blockIdx.x * blockDim.x + threadIdx.x) * 4;
    float4 c = *(const float4*)&c0[i];
    *(float4*)&g_c0[i] = c;
    *(float4*)&g_v[i]  = *(const float4*)&v0[i];
    *(float4*)&g_ss[i] = make_float4(0.f, 0.f, 0.f, 0.f);
    uint32_t p0 = (c.x > 0.f ? 0x3F80u : 0u) | (c.y > 0.f ? 0x3F800000u : 0u);
    uint32_t p1 = (c.z > 0.f ? 0x3F80u : 0u) | (c.w > 0.f ? 0x3F800000u : 0u);
    *(uint2*)&g_spk0[i] = make_uint2(p0, p1);
}

// ---------------- prep: W^T 2-way bf16 split (tiled transpose) ----------------
__global__ __launch_bounds__(256) void prep_kernel(const float* __restrict__ W) {
    __shared__ float t[32][33];
    int n0 = blockIdx.x * 32, k0 = blockIdx.y * 32;
    int tx = threadIdx.x, ty = threadIdx.y;
#pragma unroll
    for (int i = 0; i < 4; i++)
        t[ty + i * 8][tx] = W[(k0 + ty + i * 8) * NN + n0 + tx];
    __syncthreads();
#pragma unroll
    for (int i = 0; i < 4; i++) {
        float w = t[tx][ty + i * 8];            // W[k0+tx][n0+ty+i*8]
        __nv_bfloat16 hi = __float2bfloat16(w);
        __nv_bfloat16 lo = __float2bfloat16(w - __bfloat162float(hi));
        int n = n0 + ty + i * 8, k = k0 + tx;
        g_whi[n * NN + k] = hi;
        g_wlo[n * NN + k] = lo;
    }
}

// ---------------- input current: IC = rates @ iw^T (fp32 SIMT, one-time) ----------------
__global__ __launch_bounds__(256) void ic_kernel(const float* __restrict__ rates,
                                                 const float* __restrict__ iw) {
    __shared__ float As[64][33];
    __shared__ float Bs[64][33];
    int bm = blockIdx.x * 64, bn = blockIdx.y * 64;
    int tid = threadIdx.x;
    int tx = tid & 15, ty = tid >> 4;
    float acc[4][4] = {};
    for (int k0 = 0; k0 < DD; k0 += 32) {
#pragma unroll
        for (int t = 0; t < 2; t++) {
            int idx = tid + t * 256;
            int r = idx >> 3, q = idx & 7;
            float4 a = *(const float4*)&rates[(bm + r) * DD + k0 + q * 4];
            As[r][q * 4 + 0] = a.x; As[r][q * 4 + 1] = a.y;
            As[r][q * 4 + 2] = a.z; As[r][q * 4 + 3] = a.w;
            float4 b = *(const float4*)&iw[(bn + r) * DD + k0 + q * 4];
            Bs[r][q * 4 + 0] = b.x; Bs[r][q * 4 + 1] = b.y;
            Bs[r][q * 4 + 2] = b.z; Bs[r][q * 4 + 3] = b.w;
        }
        __syncthreads();
#pragma unroll
        for (int k = 0; k < 32; k++) {
            float a[4], b[4];
#pragma unroll
            for (int i = 0; i < 4; i++) a[i] = As[ty * 4 + i][k];
#pragma unroll
            for (int j = 0; j < 4; j++) b[j] = Bs[tx * 4 + j][k];
#pragma unroll
            for (int i = 0; i < 4; i++)
#pragma unroll
                for (int j = 0; j < 4; j++)
                    acc[i][j] = fmaf(a[i], b[j], acc[i][j]);
        }
        __syncthreads();
    }
#pragma unroll
    for (int i = 0; i < 4; i++)
#pragma unroll
        for (int j = 0; j < 4; j++)
            g_ic[(bm + ty * 4 + i) * NN + bn + tx * 4 + j] = acc[i][j];
}

// ---------------- fused HMMA step: rec = spk @ (Whi + Wlo), state update ----------------
// CTA tile M=128 x N=64, grid (16,8), 256 threads = 8 warps (4m x 2n), warp tile 32x32.
// K: 8 chunks of 64, 2-stage cp.async pipeline. Stage: A 16KB @0, Bhi 8KB @16384, Blo 8KB @24576.
#define STAGE_BYTES 32768

__global__ __launch_bounds__(256) void step_kernel(int s) {
    const float* __restrict__ c_in  = (s & 1) ? g_c1 : g_c0;
    float* __restrict__       c_out = (s & 1) ? g_c0 : g_c1;
    const __nv_bfloat16* __restrict__ spk_in  = (s & 1) ? g_spk1 : g_spk0;
    __nv_bfloat16* __restrict__       spk_out = (s & 1) ? g_spk0 : g_spk1;

    extern __shared__ __align__(1024) char smem[];
    uint32_t sb = smem_u32(smem);
    int tid = threadIdx.x;
    int wid = tid >> 5, lane = tid & 31;
    int bm = blockIdx.x * 128;
    int bn = blockIdx.y * 64;
    int warp_m = wid & 3, warp_n = wid >> 2;

    float acc[2][4][4] = {};

    // ---- pipelined loads ----
    auto issue = [&](int chunk) {
        uint32_t so = sb + (chunk & 1) * STAGE_BYTES;
        int k0 = chunk * 64;
#pragma unroll
        for (int t = 0; t < 4; t++) {           // A: 128 rows x 64 k bf16
            int idx = tid + t * 256;
            int r = idx >> 3, q = idx & 7;
            cp16(so + SWZ((uint32_t)(r * 128 + q * 16)),
                 &spk_in[(bm + r) * NN + k0 + q * 8]);
        }
#pragma unroll
        for (int t = 0; t < 2; t++) {           // B: 64 n-rows x 64 k, two splits
            int idx = tid + t * 256;
            int r = idx >> 3, q = idx & 7;
            uint32_t d = SWZ((uint32_t)(r * 128 + q * 16));
            cp16(so + 16384 + d, &g_whi[(bn + r) * NN + k0 + q * 8]);
            cp16(so + 24576 + d, &g_wlo[(bn + r) * NN + k0 + q * 8]);
        }
        CP_COMMIT();
    };

    issue(0);
    for (int chunk = 0; chunk < 8; chunk++) {
        if (chunk + 1 < 8) { issue(chunk + 1); CP_WAIT(1); }
        else               { CP_WAIT(0); }
        __syncthreads();

        uint32_t Ab = sb + (chunk & 1) * STAGE_BYTES;
        uint32_t Bh = Ab + 16384;
        uint32_t Bl = Ab + 24576;
#pragma unroll
        for (int kk = 0; kk < 64; kk += 16) {
            uint32_t a[2][4];
#pragma unroll
            for (int i = 0; i < 2; i++) {
                uint32_t off = (uint32_t)((warp_m * 32 + i * 16 + (lane & 15)) * 128 +
                                          (kk + (lane >> 4) * 8) * 2);
                LDSM_X4(a[i][0], a[i][1], a[i][2], a[i][3], Ab + SWZ(off));
            }
            // B address pattern (shared by both splits)
            int mtx = lane >> 3;                 // 0..3
            uint32_t boff[2];
#pragma unroll
            for (int pair = 0; pair < 2; pair++) {
                int j = pair * 2 + (mtx >> 1);
                int khalf = mtx & 1;
                boff[pair] = SWZ((uint32_t)((warp_n * 32 + j * 8 + (lane & 7)) * 128 +
                                            (kk + khalf * 8) * 2));
            }
            uint32_t b[4][2];
#pragma unroll
            for (int pair = 0; pair < 2; pair++) {
                uint32_t r0, r1, r2, r3;
                LDSM_X4(r0, r1, r2, r3, Bh + boff[pair]);
                b[pair * 2 + 0][0] = r0; b[pair * 2 + 0][1] = r1;
                b[pair * 2 + 1][0] = r2; b[pair * 2 + 1][1] = r3;
            }
#pragma unroll
            for (int i = 0; i < 2; i++)
#pragma unroll
                for (int j = 0; j < 4; j++)
                    MMA16816(acc[i][j], a[i][0], a[i][1], a[i][2], a[i][3], b[j][0], b[j][1]);
#pragma unroll
            for (int pair = 0; pair < 2; pair++) {
                uint32_t r0, r1, r2, r3;
                LDSM_X4(r0, r1, r2, r3, Bl + boff[pair]);
                b[pair * 2 + 0][0] = r0; b[pair * 2 + 0][1] = r1;
                b[pair * 2 + 1][0] = r2; b[pair * 2 + 1][1] = r3;
            }
#pragma unroll
            for (int i = 0; i < 2; i++)
#pragma unroll
                for (int j = 0; j < 4; j++)
                    MMA16816(acc[i][j], a[i][0], a[i][1], a[i][2], a[i][3], b[j][0], b[j][1]);
        }
        __syncthreads();
    }

    // ---- fused epilogue ----
    const float AS = 0.81873075307798182f;
    const float OS = 0.18126924692201818f;
    const float AM = 0.95122942450071403f;
    const float OM = 0.04877057549928599f;
    int tq = lane >> 2, tr = lane & 3;

#pragma unroll
    for (int i = 0; i < 2; i++)
#pragma unroll
        for (int j = 0; j < 4; j++)
#pragma unroll
            for (int h = 0; h < 2; h++) {
                int row = bm + warp_m * 32 + i * 16 + h * 8 + tq;
                int col = bn + warp_n * 32 + j * 8 + tr * 2;
                int idx = row * NN + col;
                float r0 = acc[i][j][h * 2 + 0];
                float r1 = acc[i][j][h * 2 + 1];
                float2 ci = *(const float2*)&c_in[idx];
                float2 ic = *(const float2*)&g_ic[idx];
                float2 vv = *(const float2*)&g_v[idx];
                float2 ss = *(const float2*)&g_ss[idx];
                float2 cn, vn;
                cn.x = AS * ci.x + OS * (ic.x + r0);
                cn.y = AS * ci.y + OS * (ic.y + r1);
                vn.x = AM * vv.x + OM * cn.x;
                vn.y = AM * vv.y + OM * cn.y;
                ss.x += (vn.x > 0.f) ? 1.f : 0.f;
                ss.y += (vn.y > 0.f) ? 1.f : 0.f;
                *(float2*)&c_out[idx] = cn;
                *(float2*)&g_v[idx]   = vn;
                *(float2*)&g_ss[idx]  = ss;
                uint32_t sp = (cn.x > 0.f ? 0x3F80u : 0u) | (cn.y > 0.f ? 0x3F800000u : 0u);
                *(uint32_t*)&spk_out[idx] = sp;
            }
}

// ---------------- finalize: out = [readout, v, c_final] ----------------
__global__ void finalize_kernel(float* __restrict__ out) {
    int i = (blockIdx.x * blockDim.x + threadIdx.x) * 4;
    float4 ss = *(const float4*)&g_ss[i];
    const float inv = 1.0f / (float)NSTEPS;
    float4 r = make_float4(ss.x * inv, ss.y * inv, ss.z * inv, ss.w * inv);
    *(float4*)&out[i]          = r;
    *(float4*)&out[BN + i]     = *(const float4*)&g_v[i];
    *(float4*)&out[2 * BN + i] = *(const float4*)&g_c0[i];  // NSTEPS even -> final c in g_c0
}

extern "C" void kernel_launch(void* const* d_in, const int* in_sizes, int n_in,
                              void* d_out, int out_size) {
    const float* rates = (const float*)d_in[0];
    const float* iw    = (const float*)d_in[1];
    const float* W     = (const float*)d_in[2];
    const float* v0    = (const float*)d_in[3];
    const float* c0    = (const float*)d_in[4];
    float* out = (float*)d_out;

    const int STEP_SMEM = 2 * STAGE_BYTES;  // 65536
    cudaFuncSetAttribute(step_kernel, cudaFuncAttributeMaxDynamicSharedMemorySize, STEP_SMEM);

    init_kernel<<<BN / 1024, 256>>>(v0, c0);
    prep_kernel<<<dim3(NN / 32, NN / 32), dim3(32, 8)>>>(W);
    ic_kernel<<<dim3(BB / 64, NN / 64), 256>>>(rates, iw);
    for (int s = 0; s < NSTEPS; s++)
        step_kernel<<<dim3(BB / 128, NN / 64), 256, STEP_SMEM>>>(s);
    finalize_kernel<<<BN / 1024, 256>>>(out);
}

// round 8
// speedup vs baseline: 3.7854x; 1.6255x over previous
#include <cuda_runtime.h>
#include <cuda_bf16.h>
#include <cstdint>

// Problem dims (fixed by setup_inputs)
#define BB 2048
#define NN 512
#define DD 256
#define NSTEPS 64
#define BN (BB * NN)
#define NCTA 128

// Persistent scratch (__device__ globals; no runtime alloc)
__device__ float g_ic[BN];
__device__ __nv_bfloat16 g_whi[NN * NN];   // W^T hi split, (n,k) row-major
__device__ __nv_bfloat16 g_wlo[NN * NN];   // W^T lo split
__device__ __nv_bfloat16 g_spk0[BN];       // spike double buffer
__device__ __nv_bfloat16 g_spk1[BN];
__device__ unsigned g_bar_count;           // zero-init
__device__ unsigned g_bar_gen;             // monotonic across calls

// ---------------------------------------------------------------- helpers
__device__ __forceinline__ uint32_t smem_u32(const void* p) {
    uint32_t a;
    asm("{ .reg .u64 t; cvta.to.shared.u64 t, %1; cvt.u32.u64 %0, t; }" : "=r"(a) : "l"(p));
    return a;
}
__device__ __forceinline__ void cp16(uint32_t dst, const void* src) {
    asm volatile("cp.async.cg.shared.global [%0], [%1], 16;" :: "r"(dst), "l"(src));
}
#define CP_COMMIT() asm volatile("cp.async.commit_group;")
#define CP_WAIT(n)  asm volatile("cp.async.wait_group %0;" :: "n"(n))

#define LDSM_X4(r0, r1, r2, r3, addr) \
    asm volatile("ldmatrix.sync.aligned.m8n8.x4.shared.b16 {%0,%1,%2,%3}, [%4];" \
                 : "=r"(r0), "=r"(r1), "=r"(r2), "=r"(r3) : "r"(addr))

#define MMA16816(d, a0, a1, a2, a3, b0, b1) \
    asm volatile("mma.sync.aligned.m16n8k16.row.col.f32.bf16.bf16.f32 " \
                 "{%0,%1,%2,%3}, {%4,%5,%6,%7}, {%8,%9}, {%0,%1,%2,%3};" \
                 : "+f"((d)[0]), "+f"((d)[1]), "+f"((d)[2]), "+f"((d)[3]) \
                 : "r"(a0), "r"(a1), "r"(a2), "r"(a3), "r"(b0), "r"(b1))

#define SWZ(o) ((o) ^ (((o) >> 3) & 0x70))

__device__ __forceinline__ unsigned ld_acq(const unsigned* p) {
    unsigned v;
    asm volatile("ld.acquire.gpu.u32 %0, [%1];" : "=r"(v) : "l"(p) : "memory");
    return v;
}
__device__ __forceinline__ void grid_barrier(int tid) {
    __syncthreads();
    if (tid == 0) {
        __threadfence();                               // publish spike writes
        unsigned my_gen = ld_acq(&g_bar_gen);
        unsigned ticket = atomicAdd(&g_bar_count, 1);
        if (ticket == NCTA - 1) {
            *(volatile unsigned*)&g_bar_count = 0;
            asm volatile("red.release.gpu.add.u32 [%0], 1;" :: "l"(&g_bar_gen) : "memory");
        } else {
            while (ld_acq(&g_bar_gen) == my_gen) __nanosleep(32);
        }
    }
    __syncthreads();
}

// ---------------------------------------------------------------- init: spikes(step0)
__global__ void init_kernel(const float* __restrict__ c0) {
    int i = (blockIdx.x * blockDim.x + threadIdx.x) * 4;
    float4 c = *(const float4*)&c0[i];
    uint32_t p0 = (c.x > 0.f ? 0x3F80u : 0u) | (c.y > 0.f ? 0x3F800000u : 0u);
    uint32_t p1 = (c.z > 0.f ? 0x3F80u : 0u) | (c.w > 0.f ? 0x3F800000u : 0u);
    *(uint2*)&g_spk0[i] = make_uint2(p0, p1);
}

// ---------------- prep: W^T 2-way bf16 split (tiled transpose) ----------------
__global__ __launch_bounds__(256) void prep_kernel(const float* __restrict__ W) {
    __shared__ float t[32][33];
    int n0 = blockIdx.x * 32, k0 = blockIdx.y * 32;
    int tx = threadIdx.x, ty = threadIdx.y;
#pragma unroll
    for (int i = 0; i < 4; i++)
        t[ty + i * 8][tx] = W[(k0 + ty + i * 8) * NN + n0 + tx];
    __syncthreads();
#pragma unroll
    for (int i = 0; i < 4; i++) {
        float w = t[tx][ty + i * 8];
        __nv_bfloat16 hi = __float2bfloat16(w);
        __nv_bfloat16 lo = __float2bfloat16(w - __bfloat162float(hi));
        int n = n0 + ty + i * 8, k = k0 + tx;
        g_whi[n * NN + k] = hi;
        g_wlo[n * NN + k] = lo;
    }
}

// ---------------- input current: IC = rates @ iw^T (one-time) ----------------
__global__ __launch_bounds__(256) void ic_kernel(const float* __restrict__ rates,
                                                 const float* __restrict__ iw) {
    __shared__ float As[64][33];
    __shared__ float Bs[64][33];
    int bm = blockIdx.x * 64, bn = blockIdx.y * 64;
    int tid = threadIdx.x;
    int tx = tid & 15, ty = tid >> 4;
    float acc[4][4] = {};
    for (int k0 = 0; k0 < DD; k0 += 32) {
#pragma unroll
        for (int t = 0; t < 2; t++) {
            int idx = tid + t * 256;
            int r = idx >> 3, q = idx & 7;
            float4 a = *(const float4*)&rates[(bm + r) * DD + k0 + q * 4];
            As[r][q * 4 + 0] = a.x; As[r][q * 4 + 1] = a.y;
            As[r][q * 4 + 2] = a.z; As[r][q * 4 + 3] = a.w;
            float4 b = *(const float4*)&iw[(bn + r) * DD + k0 + q * 4];
            Bs[r][q * 4 + 0] = b.x; Bs[r][q * 4 + 1] = b.y;
            Bs[r][q * 4 + 2] = b.z; Bs[r][q * 4 + 3] = b.w;
        }
        __syncthreads();
#pragma unroll
        for (int k = 0; k < 32; k++) {
            float a[4], b[4];
#pragma unroll
            for (int i = 0; i < 4; i++) a[i] = As[ty * 4 + i][k];
#pragma unroll
            for (int j = 0; j < 4; j++) b[j] = Bs[tx * 4 + j][k];
#pragma unroll
            for (int i = 0; i < 4; i++)
#pragma unroll
                for (int j = 0; j < 4; j++)
                    acc[i][j] = fmaf(a[i], b[j], acc[i][j]);
        }
        __syncthreads();
    }
#pragma unroll
    for (int i = 0; i < 4; i++)
#pragma unroll
        for (int j = 0; j < 4; j++)
            g_ic[(bm + ty * 4 + i) * NN + bn + tx * 4 + j] = acc[i][j];
}

// ---------------- persistent fused LSM kernel ----------------
// grid (16,8) = 128 CTAs (one per SM, 160KB smem each), 256 threads = 8 warps (4m x 2n).
// Smem: A stage0 16KB @0, A stage1 16KB @16384, Bhi 64KB @32768, Blo 64KB @98304.
// State (c,v,ss,ic) for the CTA's 128x64 tile lives in registers (32 elems/thread).
#define A_ST0 0
#define A_ST1 16384
#define B_HI 32768
#define B_LO 98304
#define LSM_SMEM 163840

__global__ __launch_bounds__(256, 1) void lsm_kernel(const float* __restrict__ v0,
                                                     const float* __restrict__ c0,
                                                     float* __restrict__ out) {
    extern __shared__ __align__(1024) char smem[];
    uint32_t sb = smem_u32(smem);
    int tid = threadIdx.x;
    int wid = tid >> 5, lane = tid & 31;
    int bm = blockIdx.x * 128;
    int bn = blockIdx.y * 64;
    int warp_m = wid & 3, warp_n = wid >> 2;
    int tq = lane >> 2, tr = lane & 3;

    // ---- one-time: load resident B strips (both splits, all 8 k-chunks) ----
    for (int chunk = 0; chunk < 8; chunk++) {
        int k0 = chunk * 64;
#pragma unroll
        for (int t = 0; t < 2; t++) {
            int idx = tid + t * 256;
            int r = idx >> 3, q = idx & 7;
            uint32_t d = (uint32_t)(chunk * 8192) + SWZ((uint32_t)(r * 128 + q * 16));
            cp16(sb + B_HI + d, &g_whi[(bn + r) * NN + k0 + q * 8]);
            cp16(sb + B_LO + d, &g_wlo[(bn + r) * NN + k0 + q * 8]);
        }
    }

    // ---- one-time: load register state for this thread's 32 output elems ----
    float c_r[32], v_r[32], ic_r[32], ss_r[32];
#pragma unroll
    for (int i = 0; i < 2; i++)
#pragma unroll
        for (int j = 0; j < 4; j++)
#pragma unroll
            for (int h = 0; h < 2; h++) {
                int s = ((i * 4 + j) * 2 + h) * 2;
                int row = bm + warp_m * 32 + i * 16 + h * 8 + tq;
                int col = bn + warp_n * 32 + j * 8 + tr * 2;
                int idx = row * NN + col;
                float2 cc = *(const float2*)&c0[idx];
                float2 vv = *(const float2*)&v0[idx];
                float2 ii = *(const float2*)&g_ic[idx];
                c_r[s] = cc.x;  c_r[s + 1] = cc.y;
                v_r[s] = vv.x;  v_r[s + 1] = vv.y;
                ic_r[s] = ii.x; ic_r[s + 1] = ii.y;
                ss_r[s] = 0.f;  ss_r[s + 1] = 0.f;
            }

    const float AS = 0.81873075307798182f;
    const float OS = 0.18126924692201818f;
    const float AM = 0.95122942450071403f;
    const float OM = 0.04877057549928599f;

    for (int s = 0; s < NSTEPS; s++) {
        const __nv_bfloat16* __restrict__ spk_in  = (s & 1) ? g_spk1 : g_spk0;
        __nv_bfloat16* __restrict__       spk_out = (s & 1) ? g_spk0 : g_spk1;

        float acc[2][4][4];
#pragma unroll
        for (int i = 0; i < 2; i++)
#pragma unroll
            for (int j = 0; j < 4; j++)
#pragma unroll
                for (int e = 0; e < 4; e++) acc[i][j][e] = 0.f;

        // A issue helper (chunk of 64 k-cols of this CTA's 128 rows)
        auto issueA = [&](int chunk) {
            uint32_t so = sb + ((chunk & 1) ? A_ST1 : A_ST0);
            int k0 = chunk * 64;
#pragma unroll
            for (int t = 0; t < 4; t++) {
                int idx = tid + t * 256;
                int r = idx >> 3, q = idx & 7;
                cp16(so + SWZ((uint32_t)(r * 128 + q * 16)),
                     &spk_in[(bm + r) * NN + k0 + q * 8]);
            }
            CP_COMMIT();
        };

        issueA(0);
        for (int chunk = 0; chunk < 8; chunk++) {
            if (chunk + 1 < 8) { issueA(chunk + 1); CP_WAIT(1); }
            else               { CP_WAIT(0); }
            __syncthreads();

            uint32_t Ab = sb + ((chunk & 1) ? A_ST1 : A_ST0);
            uint32_t Bh = sb + B_HI + chunk * 8192;
            uint32_t Bl = sb + B_LO + chunk * 8192;
#pragma unroll
            for (int kk = 0; kk < 64; kk += 16) {
                uint32_t a[2][4];
#pragma unroll
                for (int i = 0; i < 2; i++) {
                    uint32_t off = (uint32_t)((warp_m * 32 + i * 16 + (lane & 15)) * 128 +
                                              (kk + (lane >> 4) * 8) * 2);
                    LDSM_X4(a[i][0], a[i][1], a[i][2], a[i][3], Ab + SWZ(off));
                }
                int mtx = lane >> 3;
                uint32_t boff[2];
#pragma unroll
                for (int pair = 0; pair < 2; pair++) {
                    int j = pair * 2 + (mtx >> 1);
                    int khalf = mtx & 1;
                    boff[pair] = SWZ((uint32_t)((warp_n * 32 + j * 8 + (lane & 7)) * 128 +
                                                (kk + khalf * 8) * 2));
                }
                uint32_t b[4][2];
#pragma unroll
                for (int pair = 0; pair < 2; pair++) {
                    uint32_t r0, r1, r2, r3;
                    LDSM_X4(r0, r1, r2, r3, Bh + boff[pair]);
                    b[pair * 2 + 0][0] = r0; b[pair * 2 + 0][1] = r1;
                    b[pair * 2 + 1][0] = r2; b[pair * 2 + 1][1] = r3;
                }
#pragma unroll
                for (int i = 0; i < 2; i++)
#pragma unroll
                    for (int j = 0; j < 4; j++)
                        MMA16816(acc[i][j], a[i][0], a[i][1], a[i][2], a[i][3], b[j][0], b[j][1]);
#pragma unroll
                for (int pair = 0; pair < 2; pair++) {
                    uint32_t r0, r1, r2, r3;
                    LDSM_X4(r0, r1, r2, r3, Bl + boff[pair]);
                    b[pair * 2 + 0][0] = r0; b[pair * 2 + 0][1] = r1;
                    b[pair * 2 + 1][0] = r2; b[pair * 2 + 1][1] = r3;
                }
#pragma unroll
                for (int i = 0; i < 2; i++)
#pragma unroll
                    for (int j = 0; j < 4; j++)
                        MMA16816(acc[i][j], a[i][0], a[i][1], a[i][2], a[i][3], b[j][0], b[j][1]);
            }
            __syncthreads();
        }

        // ---- epilogue: register-state update + spike write ----
#pragma unroll
        for (int i = 0; i < 2; i++)
#pragma unroll
            for (int j = 0; j < 4; j++)
#pragma unroll
                for (int h = 0; h < 2; h++) {
                    int st = ((i * 4 + j) * 2 + h) * 2;
                    float r0 = acc[i][j][h * 2 + 0];
                    float r1 = acc[i][j][h * 2 + 1];
                    c_r[st]     = AS * c_r[st]     + OS * (ic_r[st]     + r0);
                    c_r[st + 1] = AS * c_r[st + 1] + OS * (ic_r[st + 1] + r1);
                    v_r[st]     = AM * v_r[st]     + OM * c_r[st];
                    v_r[st + 1] = AM * v_r[st + 1] + OM * c_r[st + 1];
                    ss_r[st]     += (v_r[st]     > 0.f) ? 1.f : 0.f;
                    ss_r[st + 1] += (v_r[st + 1] > 0.f) ? 1.f : 0.f;
                    int row = bm + warp_m * 32 + i * 16 + h * 8 + tq;
                    int col = bn + warp_n * 32 + j * 8 + tr * 2;
                    uint32_t sp = (c_r[st] > 0.f ? 0x3F80u : 0u) |
                                  (c_r[st + 1] > 0.f ? 0x3F800000u : 0u);
                    *(uint32_t*)&spk_out[row * NN + col] = sp;
                }

        grid_barrier(tid);
    }

    // ---- final output: [readout | v | c] ----
    const float inv = 1.0f / (float)NSTEPS;
#pragma unroll
    for (int i = 0; i < 2; i++)
#pragma unroll
        for (int j = 0; j < 4; j++)
#pragma unroll
            for (int h = 0; h < 2; h++) {
                int st = ((i * 4 + j) * 2 + h) * 2;
                int row = bm + warp_m * 32 + i * 16 + h * 8 + tq;
                int col = bn + warp_n * 32 + j * 8 + tr * 2;
                int idx = row * NN + col;
                *(float2*)&out[idx]          = make_float2(ss_r[st] * inv, ss_r[st + 1] * inv);
                *(float2*)&out[BN + idx]     = make_float2(v_r[st], v_r[st + 1]);
                *(float2*)&out[2 * BN + idx] = make_float2(c_r[st], c_r[st + 1]);
            }
}

extern "C" void kernel_launch(void* const* d_in, const int* in_sizes, int n_in,
                              void* d_out, int out_size) {
    const float* rates = (const float*)d_in[0];
    const float* iw    = (const float*)d_in[1];
    const float* W     = (const float*)d_in[2];
    const float* v0    = (const float*)d_in[3];
    const float* c0    = (const float*)d_in[4];
    float* out = (float*)d_out;

    cudaFuncSetAttribute(lsm_kernel, cudaFuncAttributeMaxDynamicSharedMemorySize, LSM_SMEM);

    init_kernel<<<BN / 1024, 256>>>(c0);
    prep_kernel<<<dim3(NN / 32, NN / 32), dim3(32, 8)>>>(W);
    ic_kernel<<<dim3(BB / 64, NN / 64), 256>>>(rates, iw);
    lsm_kernel<<<dim3(BB / 128, NN / 64), 256, LSM_SMEM>>>(v0, c0, out);
}